// round 4
// baseline (speedup 1.0000x reference)
#include <cuda_runtime.h>
#include <cstdint>

// GRU_12962211299468 : B=65536, T=9, I=57, H=2, O=1, fp32
// Round 4: weights in __constant__ (const-bank operands, off the LSU),
// small CTAs (8 batch elems, 96 threads, 18 KB smem) for ~12 CTAs/SM so
// load/compute phases of different CTAs interleave and hide DRAM latency.

#define T_STEPS 9
#define I_DIM   57
#define NB      8                         // batch elements per block
#define ROWS    (NB * T_STEPS)            // 72 (b,t) rows per block
#define NTHR    96                        // 3 warps
#define XFLT    (ROWS * I_DIM)            // 4104 floats, contiguous per block
#define XV4     (XFLT / 4)                // 1026 float4
#define GRID    (65536 / NB)              // 8192

__constant__ float cWih[6 * I_DIM];       // [6][57]
__constant__ float cWhh[12];              // [6][2]
__constant__ float cBih[6];
__constant__ float cBhh[6];
__constant__ float cFc[3];                // fcw0, fcw1, fcb

__device__ __forceinline__ float sigf(float v) {
    return 1.0f / (1.0f + __expf(-v));
}
__device__ __forceinline__ float tanh_ex(float v) {
    return 1.0f - 2.0f / (__expf(2.0f * v) + 1.0f);
}

__global__ __launch_bounds__(NTHR, 10) void gru_r4(
    const float* __restrict__ x,
    float* __restrict__ out)              // [B]
{
    __shared__ __align__(16) float sx[XFLT];        // 16416 B
    __shared__ float sgx[ROWS * 6];                 //  1728 B

    const int tid = threadIdx.x;
    const int b0  = blockIdx.x * NB;

    // ---- stage this block's contiguous 16416 B of x (coalesced LDG.128) ----
    {
        const float4* gsrc = reinterpret_cast<const float4*>(x) +
                             (size_t)blockIdx.x * XV4;
        float4* sdst = reinterpret_cast<float4*>(sx);
#pragma unroll 11
        for (int j = tid; j < XV4; j += NTHR)
            sdst[j] = __ldg(gsrc + j);
    }
    __syncthreads();

    // ---- projection: one (b,t) row per thread; weights from const bank ----
    if (tid < ROWS) {
        const float* row = &sx[tid * I_DIM];   // stride 57 (odd): conflict-free

        float g0 = cBih[0], g1 = cBih[1], g2 = cBih[2];
        float g3 = cBih[3], g4 = cBih[4], g5 = cBih[5];

#pragma unroll
        for (int c = 0; c < 14; ++c) {
#pragma unroll
            for (int k = 0; k < 4; ++k) {
                const int i = 4 * c + k;
                const float xv = row[i];
                g0 += cWih[0 * I_DIM + i] * xv;
                g1 += cWih[1 * I_DIM + i] * xv;
                g2 += cWih[2 * I_DIM + i] * xv;
                g3 += cWih[3 * I_DIM + i] * xv;
                g4 += cWih[4 * I_DIM + i] * xv;
                g5 += cWih[5 * I_DIM + i] * xv;
            }
        }
        {
            const float xv = row[56];
            g0 += cWih[0 * I_DIM + 56] * xv;
            g1 += cWih[1 * I_DIM + 56] * xv;
            g2 += cWih[2 * I_DIM + 56] * xv;
            g3 += cWih[3 * I_DIM + 56] * xv;
            g4 += cWih[4 * I_DIM + 56] * xv;
            g5 += cWih[5 * I_DIM + 56] * xv;
        }

        float* gq = &sgx[tid * 6];
        gq[0] = g0; gq[1] = g1; gq[2] = g2;
        gq[3] = g3; gq[4] = g4; gq[5] = g5;
    }
    __syncthreads();

    // ---- recurrence + FC: 8 threads (lanes 0-7 of warp 0) ----
    if (tid < NB) {
        const float* gp = &sgx[tid * (T_STEPS * 6)];  // stride 54: conflict-free
        float h0 = 0.0f, h1 = 0.0f;

#pragma unroll
        for (int t = 0; t < T_STEPS; ++t) {
            float q0 = gp[6 * t + 0];
            float q1 = gp[6 * t + 1];
            float q2 = gp[6 * t + 2];
            float q3 = gp[6 * t + 3];
            float q4 = gp[6 * t + 4];
            float q5 = gp[6 * t + 5];

            float a0 = cWhh[0]  * h0 + cWhh[1]  * h1 + cBhh[0];
            float a1 = cWhh[2]  * h0 + cWhh[3]  * h1 + cBhh[1];
            float a2 = cWhh[4]  * h0 + cWhh[5]  * h1 + cBhh[2];
            float a3 = cWhh[6]  * h0 + cWhh[7]  * h1 + cBhh[3];
            float a4 = cWhh[8]  * h0 + cWhh[9]  * h1 + cBhh[4];
            float a5 = cWhh[10] * h0 + cWhh[11] * h1 + cBhh[5];

            float r0 = sigf(q0 + a0);
            float r1 = sigf(q1 + a1);
            float z0 = sigf(q2 + a2);
            float z1 = sigf(q3 + a3);
            float n0 = tanh_ex(q4 + r0 * a4);
            float n1 = tanh_ex(q5 + r1 * a5);

            h0 = (1.0f - z0) * n0 + z0 * h0;
            h1 = (1.0f - z1) * n1 + z1 * h1;
        }

        out[b0 + tid] = cFc[0] * h0 + cFc[1] * h1 + cFc[2];
    }
}

extern "C" void kernel_launch(void* const* d_in, const int* in_sizes, int n_in,
                              void* d_out, int out_size) {
    const float* x   = (const float*)d_in[0];
    const float* Wih = (const float*)d_in[1];
    const float* Whh = (const float*)d_in[2];
    const float* bih = (const float*)d_in[3];
    const float* bhh = (const float*)d_in[4];
    const float* fcw = (const float*)d_in[5];
    const float* fcb = (const float*)d_in[6];
    float* out = (float*)d_out;

    (void)in_sizes; (void)n_in; (void)out_size;

    // Device-to-device copies into constant bank: graph-capturable memcpy nodes.
    cudaMemcpyToSymbolAsync(cWih, Wih, 6 * I_DIM * sizeof(float), 0,
                            cudaMemcpyDeviceToDevice, 0);
    cudaMemcpyToSymbolAsync(cWhh, Whh, 12 * sizeof(float), 0,
                            cudaMemcpyDeviceToDevice, 0);
    cudaMemcpyToSymbolAsync(cBih, bih, 6 * sizeof(float), 0,
                            cudaMemcpyDeviceToDevice, 0);
    cudaMemcpyToSymbolAsync(cBhh, bhh, 6 * sizeof(float), 0,
                            cudaMemcpyDeviceToDevice, 0);
    cudaMemcpyToSymbolAsync(cFc, fcw, 2 * sizeof(float), 0,
                            cudaMemcpyDeviceToDevice, 0);
    cudaMemcpyToSymbolAsync(cFc, fcb, sizeof(float), 2 * sizeof(float),
                            cudaMemcpyDeviceToDevice, 0);

    gru_r4<<<GRID, NTHR>>>(x, out);
}

// round 5
// speedup vs baseline: 1.3637x; 1.3637x over previous
#include <cuda_runtime.h>
#include <cstdint>

// GRU_12962211299468 : B=65536, T=9, I=57, H=2, O=1, fp32
// Round 5: persistent CTAs, double-buffered cp.async (LDGSTS) pipeline.
//   tile = 8 batch elems = 72 (b,t) rows = 16416 B contiguous x
//   while tile k computes, tile k+1 streams GMEM->SMEM via cp.async.cg
//   weights in smem (broadcast LDS, 1 cyc) -- NOT __constant__ (LDC floor=8).
// grid = 888 (6 CTAs/SM), 96 threads; ~9 tiles per CTA.

#define T_STEPS 9
#define I_DIM   57
#define NB      8
#define ROWS    (NB * T_STEPS)          // 72
#define NTHR    96
#define XFLT    (ROWS * I_DIM)          // 4104 floats / tile
#define XV4     (XFLT / 4)              // 1026 float4 / tile
#define N_TILES (65536 / NB)            // 8192
#define GRID    888                     // 148 SMs * 6 CTAs
#define WROW    60                      // padded W_ih row

__device__ __forceinline__ uint32_t s2u(const void* p) {
    uint32_t a;
    asm("{ .reg .u64 t; cvta.to.shared.u64 t, %1; cvt.u32.u64 %0, t; }"
        : "=r"(a) : "l"(p));
    return a;
}
__device__ __forceinline__ void cp16(uint32_t dst, const float4* src) {
    asm volatile("cp.async.cg.shared.global [%0], [%1], 16;"
                 :: "r"(dst), "l"(src) : "memory");
}
__device__ __forceinline__ void cp_commit() {
    asm volatile("cp.async.commit_group;" ::: "memory");
}
__device__ __forceinline__ void cp_wait1() {
    asm volatile("cp.async.wait_group 1;" ::: "memory");
}

__device__ __forceinline__ float sigf(float v) {
    return 1.0f / (1.0f + __expf(-v));
}
__device__ __forceinline__ float tanh_ex(float v) {
    return 1.0f - 2.0f / (__expf(2.0f * v) + 1.0f);
}

__global__ __launch_bounds__(NTHR, 6) void gru_r5(
    const float* __restrict__ x,
    const float* __restrict__ Wih,   // [6,57]
    const float* __restrict__ Whh,   // [6,2]
    const float* __restrict__ bih,   // [6]
    const float* __restrict__ bhh,   // [6]
    const float* __restrict__ fcw,   // [2]
    const float* __restrict__ fcb,   // [1]
    float* __restrict__ out)         // [B]
{
    __shared__ __align__(16) float buf[2][XFLT];   // 2 x 16416 B
    __shared__ float sw[6 * WROW];                 // 1440 B
    __shared__ float sgx[ROWS * 6];                // 1728 B

    const int tid = threadIdx.x;
    const uint32_t sbuf0 = s2u(&buf[0][0]);
    const uint32_t sbuf1 = s2u(&buf[1][0]);

    // ---- stage W_ih padded into smem ----
    for (int j = tid; j < 6 * WROW; j += NTHR) {
        int g = j / WROW;
        int i = j - g * WROW;
        sw[j] = (i < I_DIM) ? Wih[g * I_DIM + i] : 0.0f;
    }

    // ---- hoist small params into registers (broadcast LDG, L1-resident) ----
    const float bi0 = __ldg(bih + 0), bi1 = __ldg(bih + 1), bi2 = __ldg(bih + 2);
    const float bi3 = __ldg(bih + 3), bi4 = __ldg(bih + 4), bi5 = __ldg(bih + 5);
    const float w00 = __ldg(Whh + 0),  w01 = __ldg(Whh + 1);
    const float w10 = __ldg(Whh + 2),  w11 = __ldg(Whh + 3);
    const float w20 = __ldg(Whh + 4),  w21 = __ldg(Whh + 5);
    const float w30 = __ldg(Whh + 6),  w31 = __ldg(Whh + 7);
    const float w40 = __ldg(Whh + 8),  w41 = __ldg(Whh + 9);
    const float w50 = __ldg(Whh + 10), w51 = __ldg(Whh + 11);
    const float bh0 = __ldg(bhh + 0), bh1 = __ldg(bhh + 1), bh2 = __ldg(bhh + 2);
    const float bh3 = __ldg(bhh + 3), bh4 = __ldg(bhh + 4), bh5 = __ldg(bhh + 5);
    const float fw0 = __ldg(fcw + 0), fw1 = __ldg(fcw + 1), fb = __ldg(fcb);

    const float4* xv = reinterpret_cast<const float4*>(x);

    // ---- prologue: prefetch tiles t0 and t0+GRID ----
    const int t0 = blockIdx.x;
    {
        const float4* src = xv + (size_t)t0 * XV4;
        for (int j = tid; j < XV4; j += NTHR)
            cp16(sbuf0 + 16u * j, src + j);
    }
    cp_commit();
    if (t0 + GRID < N_TILES) {
        const float4* src = xv + (size_t)(t0 + GRID) * XV4;
        for (int j = tid; j < XV4; j += NTHR)
            cp16(sbuf1 + 16u * j, src + j);
    }
    cp_commit();

    int p = 0;
    for (int tile = t0; tile < N_TILES; tile += GRID) {
        cp_wait1();          // tile 'tile' (oldest pending group) complete
        __syncthreads();     // make all threads' copies visible block-wide

        const float* bx = buf[p];

        // ---- projection: one (b,t) row per thread (tid < 72) ----
        if (tid < ROWS) {
            const float* row = bx + tid * I_DIM;  // stride 57: conflict-free
            float g0 = bi0, g1 = bi1, g2 = bi2, g3 = bi3, g4 = bi4, g5 = bi5;
#pragma unroll
            for (int c = 0; c < 14; ++c) {
                float x0 = row[4 * c + 0];
                float x1 = row[4 * c + 1];
                float x2 = row[4 * c + 2];
                float x3 = row[4 * c + 3];
                float4 v;
                v = *reinterpret_cast<const float4*>(&sw[0 * WROW + 4 * c]);
                g0 += v.x * x0 + v.y * x1 + v.z * x2 + v.w * x3;
                v = *reinterpret_cast<const float4*>(&sw[1 * WROW + 4 * c]);
                g1 += v.x * x0 + v.y * x1 + v.z * x2 + v.w * x3;
                v = *reinterpret_cast<const float4*>(&sw[2 * WROW + 4 * c]);
                g2 += v.x * x0 + v.y * x1 + v.z * x2 + v.w * x3;
                v = *reinterpret_cast<const float4*>(&sw[3 * WROW + 4 * c]);
                g3 += v.x * x0 + v.y * x1 + v.z * x2 + v.w * x3;
                v = *reinterpret_cast<const float4*>(&sw[4 * WROW + 4 * c]);
                g4 += v.x * x0 + v.y * x1 + v.z * x2 + v.w * x3;
                v = *reinterpret_cast<const float4*>(&sw[5 * WROW + 4 * c]);
                g5 += v.x * x0 + v.y * x1 + v.z * x2 + v.w * x3;
            }
            {
                float xs = row[56];
                g0 += sw[0 * WROW + 56] * xs;
                g1 += sw[1 * WROW + 56] * xs;
                g2 += sw[2 * WROW + 56] * xs;
                g3 += sw[3 * WROW + 56] * xs;
                g4 += sw[4 * WROW + 56] * xs;
                g5 += sw[5 * WROW + 56] * xs;
            }
            float* gq = &sgx[tid * 6];
            gq[0] = g0; gq[1] = g1; gq[2] = g2;
            gq[3] = g3; gq[4] = g4; gq[5] = g5;
        }
        __syncthreads();     // buf[p] fully consumed; sgx published

        // ---- prefetch tile+2*GRID into the buffer just freed ----
        const int nxt2 = tile + 2 * GRID;
        if (nxt2 < N_TILES) {
            const float4* src = xv + (size_t)nxt2 * XV4;
            const uint32_t sb = p ? sbuf1 : sbuf0;
            for (int j = tid; j < XV4; j += NTHR)
                cp16(sb + 16u * j, src + j);
        }
        cp_commit();         // commit every iteration (empty group if none issued)

        // ---- recurrence + FC: lanes 24-31 of warp 2 (idle in projection) ----
        if (tid >= 88) {
            const int j = tid - 88;
            const float* gp = &sgx[j * (T_STEPS * 6)];  // stride 54: conflict-free
            float h0 = 0.0f, h1 = 0.0f;
#pragma unroll
            for (int t = 0; t < T_STEPS; ++t) {
                float q0 = gp[6 * t + 0];
                float q1 = gp[6 * t + 1];
                float q2 = gp[6 * t + 2];
                float q3 = gp[6 * t + 3];
                float q4 = gp[6 * t + 4];
                float q5 = gp[6 * t + 5];

                float a0 = w00 * h0 + w01 * h1 + bh0;
                float a1 = w10 * h0 + w11 * h1 + bh1;
                float a2 = w20 * h0 + w21 * h1 + bh2;
                float a3 = w30 * h0 + w31 * h1 + bh3;
                float a4 = w40 * h0 + w41 * h1 + bh4;
                float a5 = w50 * h0 + w51 * h1 + bh5;

                float r0 = sigf(q0 + a0);
                float r1 = sigf(q1 + a1);
                float z0 = sigf(q2 + a2);
                float z1 = sigf(q3 + a3);
                float n0 = tanh_ex(q4 + r0 * a4);
                float n1 = tanh_ex(q5 + r1 * a5);

                h0 = (1.0f - z0) * n0 + z0 * h0;
                h1 = (1.0f - z1) * n1 + z1 * h1;
            }
            out[tile * NB + j] = fw0 * h0 + fw1 * h1 + fb;
        }

        p ^= 1;
    }
}

extern "C" void kernel_launch(void* const* d_in, const int* in_sizes, int n_in,
                              void* d_out, int out_size) {
    const float* x   = (const float*)d_in[0];
    const float* Wih = (const float*)d_in[1];
    const float* Whh = (const float*)d_in[2];
    const float* bih = (const float*)d_in[3];
    const float* bhh = (const float*)d_in[4];
    const float* fcw = (const float*)d_in[5];
    const float* fcb = (const float*)d_in[6];
    float* out = (float*)d_out;

    (void)in_sizes; (void)n_in; (void)out_size;

    gru_r5<<<GRID, NTHR>>>(x, Wih, Whh, bih, bhh, fcw, fcb, out);
}